// round 10
// baseline (speedup 1.0000x reference)
#include <cuda_runtime.h>
#include <cuda_fp16.h>
#include <cstdint>
#include <cstddef>

// ---------------- static problem shape ----------------
constexpr int BSZ = 2;
constexpr int NQ  = 21760;
constexpr int MR  = BSZ * NQ;      // 43520 rows
constexpr int D   = 256;
constexpr int NH  = 8;
constexpr int DH  = 32;
constexpr int NFUSED = 384;        // 256 offs + 128 attn logits

__device__ __constant__ int c_LW[4] = {128, 64, 32, 16};
__device__ __constant__ int c_LH[4] = {128, 64, 32, 16};
__device__ __constant__ int c_LS[4] = {0, 16384, 20480, 21504};

// ---------------- scratch ----------------
__device__ __half g_vth[(size_t)BSZ * NH * NQ * DH];    // v transposed: [b][h][pos][c] fp16
__device__ float  g_P [(size_t)MR * NFUSED];            // raw offs(256) + attn logits(128)
__device__ float  g_tmp[(size_t)MR * D];                // attention output before Wout
__device__ float  g_Wf[D * NFUSED];                     // fused [Wo | Wa]
__device__ float  g_bf[NFUSED];                         // fused [bo | ba]

// ---------------- helpers ----------------
__device__ __forceinline__ void mma_tf32(float& c0, float& c1, float& c2, float& c3,
                                         uint32_t a0, uint32_t a1, uint32_t a2, uint32_t a3,
                                         uint32_t b0, uint32_t b1) {
    asm volatile(
        "mma.sync.aligned.m16n8k8.row.col.f32.tf32.tf32.f32 "
        "{%0,%1,%2,%3}, {%4,%5,%6,%7}, {%8,%9}, {%0,%1,%2,%3};"
        : "+f"(c0), "+f"(c1), "+f"(c2), "+f"(c3)
        : "r"(a0), "r"(a1), "r"(a2), "r"(a3), "r"(b0), "r"(b1));
}

__device__ __forceinline__ void cp16(void* smem_dst, const void* gsrc) {
    unsigned d = (unsigned)__cvta_generic_to_shared(smem_dst);
    asm volatile("cp.async.cg.shared.global [%0], [%1], 16;" :: "r"(d), "l"(gsrc));
}

__device__ __forceinline__ float4 ld4h(const __half* p) {
    const uint2 u = *reinterpret_cast<const uint2*>(p);
    const __half2 h0 = *reinterpret_cast<const __half2*>(&u.x);
    const __half2 h1 = *reinterpret_cast<const __half2*>(&u.y);
    const float2 f0 = __half22float2(h0);
    const float2 f1 = __half22float2(h1);
    return make_float4(f0.x, f0.y, f1.x, f1.y);
}

// ---------------- pack fused weight ----------------
__global__ void pack_w_kernel(const float* __restrict__ Wo, const float* __restrict__ bo,
                              const float* __restrict__ Wa, const float* __restrict__ ba) {
    int i = blockIdx.x * blockDim.x + threadIdx.x;
    if (i < D * NFUSED) {
        int k = i / NFUSED, n = i % NFUSED;
        g_Wf[i] = (n < 256) ? Wo[k * 256 + n] : Wa[k * 128 + (n - 256)];
    }
    if (i < NFUSED) g_bf[i] = (i < 256) ? bo[i] : ba[i - 256];
}

// ---------------- tf32 tensor-core GEMM, 3-stage cp.async pipeline ----------------
// Tile: BM=128, BN=64, BK=16.  8 warps as 4(M) x 2(N), warp tile 32x32.
// Both A and B fragments: raw fp32 bits (HW truncates to tf32) -- no cvt in loop.
// One __syncthreads per k-iter (3-stage rotation makes the single barrier safe).
// MODE 0: A=value, W=Wv   -> scatter into g_vth [b][h][pos][c] as fp16
// MODE 1: A=query, W=g_Wf -> g_P row-major
// MODE 2: A=g_tmp, W=Wout -> Cout = acc + bias + addin (residual)
template<int MODE>
__global__ __launch_bounds__(256)
void gemm_tc(const float* __restrict__ Ain, const float* __restrict__ Win,
             const float* __restrict__ biasin, const float* __restrict__ addin,
             float* __restrict__ Cout, int N)
{
    constexpr int K = D;
    const float* A    = (MODE == 2) ? g_tmp : Ain;
    const float* W    = (MODE == 1) ? g_Wf  : Win;
    const float* bias = (MODE == 1) ? g_bf  : biasin;

    __shared__ float As[3][128][20];   // [stage][m][k], stride 20 -> conflict-free
    __shared__ float Bs[3][16][72];    // [stage][k][n], stride 72 -> conflict-free

    const int tid  = threadIdx.x;
    const int warp = tid >> 5;
    const int lane = tid & 31;
    const int wm   = (warp & 3) * 32;
    const int wn   = (warp >> 2) * 32;
    const int m0   = blockIdx.x * 128;
    const int n0   = blockIdx.y * 64;

    const int ar = tid >> 2;   // 0..63 (and +64)
    const int aq = tid & 3;
    const int br = tid >> 4;   // 0..15
    const int bc = tid & 15;

    float c[2][4][4];
    #pragma unroll
    for (int mf = 0; mf < 2; ++mf)
        #pragma unroll
        for (int nf = 0; nf < 4; ++nf)
            #pragma unroll
            for (int i = 0; i < 4; ++i) c[mf][nf][i] = 0.f;

    auto load_stage = [&](int kt, int buf) {
        const int kk = kt * 16;
        cp16(&As[buf][ar][aq * 4],      A + (size_t)(m0 + ar) * K + kk + aq * 4);
        cp16(&As[buf][ar + 64][aq * 4], A + (size_t)(m0 + ar + 64) * K + kk + aq * 4);
        cp16(&Bs[buf][br][bc * 4],      W + (size_t)(kk + br) * N + n0 + bc * 4);
        asm volatile("cp.async.commit_group;" ::: "memory");
    };

    load_stage(0, 0);
    load_stage(1, 1);

    for (int kt = 0; kt < 16; ++kt) {
        const int buf = kt % 3;
        if (kt < 15) {
            asm volatile("cp.async.wait_group 1;" ::: "memory");
        } else {
            asm volatile("cp.async.wait_group 0;" ::: "memory");
        }
        __syncthreads();

        #pragma unroll
        for (int kc = 0; kc < 16; kc += 8) {
            uint32_t a[2][4], b[4][2];
            const int arow = wm + (lane >> 2);
            const int acol = kc + (lane & 3);
            #pragma unroll
            for (int mf = 0; mf < 2; ++mf) {
                const int r0 = arow + mf * 16;
                a[mf][0] = __float_as_uint(As[buf][r0    ][acol    ]);
                a[mf][1] = __float_as_uint(As[buf][r0 + 8][acol    ]);
                a[mf][2] = __float_as_uint(As[buf][r0    ][acol + 4]);
                a[mf][3] = __float_as_uint(As[buf][r0 + 8][acol + 4]);
            }
            #pragma unroll
            for (int nf = 0; nf < 4; ++nf) {
                const int nn = wn + nf * 8 + (lane >> 2);
                b[nf][0] = __float_as_uint(Bs[buf][acol    ][nn]);
                b[nf][1] = __float_as_uint(Bs[buf][acol + 4][nn]);
            }
            #pragma unroll
            for (int mf = 0; mf < 2; ++mf)
                #pragma unroll
                for (int nf = 0; nf < 4; ++nf)
                    mma_tf32(c[mf][nf][0], c[mf][nf][1], c[mf][nf][2], c[mf][nf][3],
                             a[mf][0], a[mf][1], a[mf][2], a[mf][3],
                             b[nf][0], b[nf][1]);
        }

        if (kt + 2 < 16) load_stage(kt + 2, (kt + 2) % 3);
    }

    // epilogue
    #pragma unroll
    for (int mf = 0; mf < 2; ++mf) {
        #pragma unroll
        for (int nf = 0; nf < 4; ++nf) {
            const int cb = n0 + wn + nf * 8 + 2 * (lane & 3);
            const float2 b2 = *reinterpret_cast<const float2*>(bias + cb);
            #pragma unroll
            for (int half_i = 0; half_i < 2; ++half_i) {
                const int row = m0 + wm + mf * 16 + (lane >> 2) + half_i * 8;
                const float v0 = c[mf][nf][half_i * 2 + 0] + b2.x;
                const float v1 = c[mf][nf][half_i * 2 + 1] + b2.y;
                if (MODE == 0) {
                    const int bb  = row / NQ;
                    const int pos = row - bb * NQ;
                    const __half2 hv = __floats2half2_rn(v0, v1);
                    *reinterpret_cast<__half2*>(
                        g_vth + ((size_t)(bb * NH + (cb >> 5)) * NQ + pos) * DH + (cb & 31)) = hv;
                } else if (MODE == 1) {
                    *reinterpret_cast<float2*>(g_P + (size_t)row * NFUSED + cb)
                        = make_float2(v0, v1);
                } else {
                    const float2 q2 = *reinterpret_cast<const float2*>(
                        addin + (size_t)row * D + cb);
                    *reinterpret_cast<float2*>(Cout + (size_t)row * D + cb)
                        = make_float2(v0 + q2.x, v1 + q2.y);
                }
            }
        }
    }
}

// ---------------- fused softmax + coords + bilinear gather ----------------
// R3/R7 structure (measured best); v now fp16 -> corner loads are 8B uint2.
__global__ __launch_bounds__(256, 6)
void sample_kernel(const float* __restrict__ refp) {
    const int gwarp = blockIdx.x * 8 + (threadIdx.x >> 5);
    const int lane  = threadIdx.x & 31;
    if (gwarp >= MR * NH) return;
    const int h  = gwarp & 7;
    const int bq = gwarp >> 3;
    const int b  = (bq >= NQ);

    const float* Prow = g_P + (size_t)bq * NFUSED;
    const int i  = lane & 15;          // point index (lanes 16-31 mirror)
    const int il = i >> 2;

    // softmax over the 16 logits of this head
    float lg = Prow[256 + h * 16 + i];
    float mx = lg;
    #pragma unroll
    for (int off = 8; off; off >>= 1)
        mx = fmaxf(mx, __shfl_xor_sync(0xffffffffu, mx, off));
    float e = __expf(lg - mx);
    float ssum = e;
    #pragma unroll
    for (int off = 8; off; off >>= 1)
        ssum += __shfl_xor_sync(0xffffffffu, ssum, off);
    const float wgt = e / ssum;

    // pixel coords for this lane's point
    const float2 off2 = *reinterpret_cast<const float2*>(Prow + h * 32 + i * 2);
    const float2 ref2 = *reinterpret_cast<const float2*>(refp + (size_t)bq * 8 + il * 2);
    const float px = ref2.x * (float)c_LW[il] + off2.x - 0.5f;
    const float py = ref2.y * (float)c_LH[il] + off2.y - 0.5f;

    const int pgrp = lane >> 3;       // which point of the level this group does
    const int cq   = (lane & 7) * 4;  // channel quad
    const __half* vb = g_vth + ((size_t)(b * NH + h) * NQ) * DH + cq;

    float4 acc = make_float4(0.f, 0.f, 0.f, 0.f);
    #pragma unroll
    for (int j = 0; j < 4; ++j) {     // j = level
        const int Wl = c_LW[j], Hl = c_LH[j], st = c_LS[j];
        const int p  = j * 4 + pgrp;
        const float sx = __shfl_sync(0xffffffffu, px,  p);
        const float sy = __shfl_sync(0xffffffffu, py,  p);
        const float sw = __shfl_sync(0xffffffffu, wgt, p);

        const float xf = floorf(sx), yf = floorf(sy);
        const int   x0 = (int)xf,    y0 = (int)yf;
        const float wx1 = sx - xf,   wy1 = sy - yf;
        const float wx0 = 1.f - wx1, wy0 = 1.f - wy1;
        const int x1 = x0 + 1, y1 = y0 + 1;
        const bool vx0 = (x0 >= 0) && (x0 < Wl);
        const bool vx1 = (x1 >= 0) && (x1 < Wl);
        const bool vy0 = (y0 >= 0) && (y0 < Hl);
        const bool vy1 = (y1 >= 0) && (y1 < Hl);

        const float w00 = sw * wy0 * wx0;
        const float w01 = sw * wy0 * wx1;
        const float w10 = sw * wy1 * wx0;
        const float w11 = sw * wy1 * wx1;

        float4 v00 = make_float4(0,0,0,0), v01 = v00, v10 = v00, v11 = v00;
        const __half* r0 = vb + (size_t)(st + y0 * Wl) * DH;
        const __half* r1 = vb + (size_t)(st + y1 * Wl) * DH;
        if (vy0 && vx0) v00 = ld4h(r0 + (size_t)x0 * DH);
        if (vy0 && vx1) v01 = ld4h(r0 + (size_t)x1 * DH);
        if (vy1 && vx0) v10 = ld4h(r1 + (size_t)x0 * DH);
        if (vy1 && vx1) v11 = ld4h(r1 + (size_t)x1 * DH);

        acc.x += w00 * v00.x + w01 * v01.x + w10 * v10.x + w11 * v11.x;
        acc.y += w00 * v00.y + w01 * v01.y + w10 * v10.y + w11 * v11.y;
        acc.z += w00 * v00.z + w01 * v01.z + w10 * v10.z + w11 * v11.z;
        acc.w += w00 * v00.w + w01 * v01.w + w10 * v10.w + w11 * v11.w;
    }

    // reduce across the 4 point-groups (lanes xor 8, 16)
    #pragma unroll
    for (int off = 8; off <= 16; off <<= 1) {
        acc.x += __shfl_xor_sync(0xffffffffu, acc.x, off);
        acc.y += __shfl_xor_sync(0xffffffffu, acc.y, off);
        acc.z += __shfl_xor_sync(0xffffffffu, acc.z, off);
        acc.w += __shfl_xor_sync(0xffffffffu, acc.w, off);
    }
    if (lane < 8)
        *reinterpret_cast<float4*>(g_tmp + (size_t)bq * D + h * DH + cq) = acc;
}

// ---------------- launch ----------------
extern "C" void kernel_launch(void* const* d_in, const int* in_sizes, int n_in,
                              void* d_out, int out_size) {
    const float* query = (const float*)d_in[0];
    const float* value = (const float*)d_in[1];
    const float* refp  = (const float*)d_in[2];
    const float* Wv   = (const float*)d_in[5];
    const float* bv   = (const float*)d_in[6];
    const float* Wo   = (const float*)d_in[7];
    const float* bo   = (const float*)d_in[8];
    const float* Wa   = (const float*)d_in[9];
    const float* ba   = (const float*)d_in[10];
    const float* Wout = (const float*)d_in[11];
    const float* bout = (const float*)d_in[12];
    float* out = (float*)d_out;

    pack_w_kernel<<<(D * NFUSED + 255) / 256, 256>>>(Wo, bo, Wa, ba);

    gemm_tc<0><<<dim3(MR / 128, 256 / 64), 256>>>(value, Wv, bv, nullptr, nullptr, 256);
    gemm_tc<1><<<dim3(MR / 128, NFUSED / 64), 256>>>(query, nullptr, nullptr, nullptr, nullptr, NFUSED);

    sample_kernel<<<MR * NH / 8, 256>>>(refp);

    gemm_tc<2><<<dim3(MR / 128, 256 / 64), 256>>>(nullptr, Wout, bout, query, out, 256);
}

// round 11
// speedup vs baseline: 1.6024x; 1.6024x over previous
#include <cuda_runtime.h>
#include <cstdint>
#include <cstddef>

// ---------------- static problem shape ----------------
constexpr int BSZ = 2;
constexpr int NQ  = 21760;
constexpr int MR  = BSZ * NQ;      // 43520 rows
constexpr int D   = 256;
constexpr int NH  = 8;
constexpr int DH  = 32;
constexpr int NFUSED = 384;        // 256 offs + 128 attn logits

__device__ __constant__ int c_LW[4] = {128, 64, 32, 16};
__device__ __constant__ int c_LH[4] = {128, 64, 32, 16};
__device__ __constant__ int c_LS[4] = {0, 16384, 20480, 21504};

// ---------------- scratch ----------------
__device__ float  g_vt[(size_t)BSZ * NH * NQ * DH];     // v transposed: [b][h][pos][c]
__device__ float  g_P [(size_t)MR * NFUSED];            // raw offs(256) + attn logits(128)
__device__ float  g_tmp[(size_t)MR * D];                // attention output before Wout
__device__ float  g_Wf[D * NFUSED];                     // fused [Wo | Wa]
__device__ float  g_bf[NFUSED];                         // fused [bo | ba]

// ---------------- helpers ----------------
__device__ __forceinline__ void mma_tf32(float& c0, float& c1, float& c2, float& c3,
                                         uint32_t a0, uint32_t a1, uint32_t a2, uint32_t a3,
                                         uint32_t b0, uint32_t b1) {
    asm volatile(
        "mma.sync.aligned.m16n8k8.row.col.f32.tf32.tf32.f32 "
        "{%0,%1,%2,%3}, {%4,%5,%6,%7}, {%8,%9}, {%0,%1,%2,%3};"
        : "+f"(c0), "+f"(c1), "+f"(c2), "+f"(c3)
        : "r"(a0), "r"(a1), "r"(a2), "r"(a3), "r"(b0), "r"(b1));
}

__device__ __forceinline__ void cp16(void* smem_dst, const void* gsrc) {
    unsigned d = (unsigned)__cvta_generic_to_shared(smem_dst);
    asm volatile("cp.async.cg.shared.global [%0], [%1], 16;" :: "r"(d), "l"(gsrc));
}

// ---------------- pack fused weight ----------------
__global__ void pack_w_kernel(const float* __restrict__ Wo, const float* __restrict__ bo,
                              const float* __restrict__ Wa, const float* __restrict__ ba) {
    int i = blockIdx.x * blockDim.x + threadIdx.x;
    if (i < D * NFUSED) {
        int k = i / NFUSED, n = i % NFUSED;
        g_Wf[i] = (n < 256) ? Wo[k * 256 + n] : Wa[k * 128 + (n - 256)];
    }
    if (i < NFUSED) g_bf[i] = (i < 256) ? bo[i] : ba[i - 256];
}

// ---------------- tf32 tensor-core GEMM, 3-stage cp.async pipeline ----------------
// Tile: BM=128, BN=64, BK=16.  8 warps as 4(M) x 2(N), warp tile 32x32.
// Both A and B fragments: raw fp32 bits (HW truncates to tf32) -- no cvt in loop.
// One __syncthreads per k-iter (3-stage rotation makes the single barrier safe).
// MODE 0: A=value, W=Wv   -> scatter into g_vt [b][h][pos][c]
// MODE 1: A=query, W=g_Wf -> g_P row-major
// MODE 2: A=g_tmp, W=Wout -> Cout = acc + bias + addin (residual)
template<int MODE>
__global__ __launch_bounds__(256)
void gemm_tc(const float* __restrict__ Ain, const float* __restrict__ Win,
             const float* __restrict__ biasin, const float* __restrict__ addin,
             float* __restrict__ Cout, int N)
{
    constexpr int K = D;
    const float* A    = (MODE == 2) ? g_tmp : Ain;
    const float* W    = (MODE == 1) ? g_Wf  : Win;
    const float* bias = (MODE == 1) ? g_bf  : biasin;

    __shared__ float As[3][128][20];   // [stage][m][k], stride 20 -> conflict-free
    __shared__ float Bs[3][16][72];    // [stage][k][n], stride 72 -> conflict-free

    const int tid  = threadIdx.x;
    const int warp = tid >> 5;
    const int lane = tid & 31;
    const int wm   = (warp & 3) * 32;
    const int wn   = (warp >> 2) * 32;
    const int m0   = blockIdx.x * 128;
    const int n0   = blockIdx.y * 64;

    const int ar = tid >> 2;   // 0..63 (and +64)
    const int aq = tid & 3;
    const int br = tid >> 4;   // 0..15
    const int bc = tid & 15;

    float c[2][4][4];
    #pragma unroll
    for (int mf = 0; mf < 2; ++mf)
        #pragma unroll
        for (int nf = 0; nf < 4; ++nf)
            #pragma unroll
            for (int i = 0; i < 4; ++i) c[mf][nf][i] = 0.f;

    auto load_stage = [&](int kt, int buf) {
        const int kk = kt * 16;
        cp16(&As[buf][ar][aq * 4],      A + (size_t)(m0 + ar) * K + kk + aq * 4);
        cp16(&As[buf][ar + 64][aq * 4], A + (size_t)(m0 + ar + 64) * K + kk + aq * 4);
        cp16(&Bs[buf][br][bc * 4],      W + (size_t)(kk + br) * N + n0 + bc * 4);
        asm volatile("cp.async.commit_group;" ::: "memory");
    };

    load_stage(0, 0);
    load_stage(1, 1);

    for (int kt = 0; kt < 16; ++kt) {
        const int buf = kt % 3;
        if (kt < 15) {
            asm volatile("cp.async.wait_group 1;" ::: "memory");
        } else {
            asm volatile("cp.async.wait_group 0;" ::: "memory");
        }
        __syncthreads();

        #pragma unroll
        for (int kc = 0; kc < 16; kc += 8) {
            uint32_t a[2][4], b[4][2];
            const int arow = wm + (lane >> 2);
            const int acol = kc + (lane & 3);
            #pragma unroll
            for (int mf = 0; mf < 2; ++mf) {
                const int r0 = arow + mf * 16;
                a[mf][0] = __float_as_uint(As[buf][r0    ][acol    ]);
                a[mf][1] = __float_as_uint(As[buf][r0 + 8][acol    ]);
                a[mf][2] = __float_as_uint(As[buf][r0    ][acol + 4]);
                a[mf][3] = __float_as_uint(As[buf][r0 + 8][acol + 4]);
            }
            #pragma unroll
            for (int nf = 0; nf < 4; ++nf) {
                const int nn = wn + nf * 8 + (lane >> 2);
                b[nf][0] = __float_as_uint(Bs[buf][acol    ][nn]);
                b[nf][1] = __float_as_uint(Bs[buf][acol + 4][nn]);
            }
            #pragma unroll
            for (int mf = 0; mf < 2; ++mf)
                #pragma unroll
                for (int nf = 0; nf < 4; ++nf)
                    mma_tf32(c[mf][nf][0], c[mf][nf][1], c[mf][nf][2], c[mf][nf][3],
                             a[mf][0], a[mf][1], a[mf][2], a[mf][3],
                             b[nf][0], b[nf][1]);
        }

        if (kt + 2 < 16) load_stage(kt + 2, (kt + 2) % 3);
    }

    // epilogue
    #pragma unroll
    for (int mf = 0; mf < 2; ++mf) {
        #pragma unroll
        for (int nf = 0; nf < 4; ++nf) {
            const int cb = n0 + wn + nf * 8 + 2 * (lane & 3);
            const float2 b2 = *reinterpret_cast<const float2*>(bias + cb);
            #pragma unroll
            for (int half_i = 0; half_i < 2; ++half_i) {
                const int row = m0 + wm + mf * 16 + (lane >> 2) + half_i * 8;
                const float v0 = c[mf][nf][half_i * 2 + 0] + b2.x;
                const float v1 = c[mf][nf][half_i * 2 + 1] + b2.y;
                if (MODE == 0) {
                    const int bb  = row / NQ;
                    const int pos = row - bb * NQ;
                    float2* dst = reinterpret_cast<float2*>(
                        g_vt + ((size_t)(bb * NH + (cb >> 5)) * NQ + pos) * DH + (cb & 31));
                    *dst = make_float2(v0, v1);
                } else if (MODE == 1) {
                    *reinterpret_cast<float2*>(g_P + (size_t)row * NFUSED + cb)
                        = make_float2(v0, v1);
                } else {
                    const float2 q2 = *reinterpret_cast<const float2*>(
                        addin + (size_t)row * D + cb);
                    *reinterpret_cast<float2*>(Cout + (size_t)row * D + cb)
                        = make_float2(v0 + q2.x, v1 + q2.y);
                }
            }
        }
    }
}

// ---------------- fused softmax + coords + bilinear gather ----------------
// R3/R7 structure (measured best).  Micro-opts only: sw folded into row
// weights (8->6 FMUL per level), unsigned-compare bounds (1 SETP per test),
// 7-blocks-min occupancy hint (regs<=36, occ ~78%).
__global__ __launch_bounds__(256, 7)
void sample_kernel(const float* __restrict__ refp) {
    const int gwarp = blockIdx.x * 8 + (threadIdx.x >> 5);
    const int lane  = threadIdx.x & 31;
    if (gwarp >= MR * NH) return;
    const int h  = gwarp & 7;
    const int bq = gwarp >> 3;
    const int b  = (bq >= NQ);

    const float* Prow = g_P + (size_t)bq * NFUSED;
    const int i  = lane & 15;          // point index (lanes 16-31 mirror)
    const int il = i >> 2;

    // softmax over the 16 logits of this head
    float lg = Prow[256 + h * 16 + i];
    float mx = lg;
    #pragma unroll
    for (int off = 8; off; off >>= 1)
        mx = fmaxf(mx, __shfl_xor_sync(0xffffffffu, mx, off));
    float e = __expf(lg - mx);
    float ssum = e;
    #pragma unroll
    for (int off = 8; off; off >>= 1)
        ssum += __shfl_xor_sync(0xffffffffu, ssum, off);
    const float wgt = e / ssum;

    // pixel coords for this lane's point
    const float2 off2 = *reinterpret_cast<const float2*>(Prow + h * 32 + i * 2);
    const float2 ref2 = *reinterpret_cast<const float2*>(refp + (size_t)bq * 8 + il * 2);
    const float px = ref2.x * (float)c_LW[il] + off2.x - 0.5f;
    const float py = ref2.y * (float)c_LH[il] + off2.y - 0.5f;

    const int pgrp = lane >> 3;       // which point of the level this group does
    const int cq   = (lane & 7) * 4;  // channel quad
    const float* vb = g_vt + ((size_t)(b * NH + h) * NQ) * DH + cq;

    float4 acc = make_float4(0.f, 0.f, 0.f, 0.f);
    #pragma unroll
    for (int j = 0; j < 4; ++j) {     // j = level
        const int Wl = c_LW[j], Hl = c_LH[j], st = c_LS[j];
        const int p  = j * 4 + pgrp;
        const float sx = __shfl_sync(0xffffffffu, px,  p);
        const float sy = __shfl_sync(0xffffffffu, py,  p);
        const float sw = __shfl_sync(0xffffffffu, wgt, p);

        const float xf = floorf(sx), yf = floorf(sy);
        const int   x0 = (int)xf,    y0 = (int)yf;
        const float wx1 = sx - xf,   wy1 = sy - yf;
        const float wx0 = 1.f - wx1, wy0 = 1.f - wy1;
        const int x1 = x0 + 1, y1 = y0 + 1;
        const bool vx0 = (unsigned)x0 < (unsigned)Wl;
        const bool vx1 = (unsigned)x1 < (unsigned)Wl;
        const bool vy0 = (unsigned)y0 < (unsigned)Hl;
        const bool vy1 = (unsigned)y1 < (unsigned)Hl;

        const float swy0 = sw * wy0;
        const float swy1 = sw * wy1;
        const float w00 = swy0 * wx0;
        const float w01 = swy0 * wx1;
        const float w10 = swy1 * wx0;
        const float w11 = swy1 * wx1;

        float4 v00 = make_float4(0,0,0,0), v01 = v00, v10 = v00, v11 = v00;
        const float* r0 = vb + (size_t)(st + y0 * Wl) * DH;
        const float* r1 = vb + (size_t)(st + y1 * Wl) * DH;
        if (vy0 && vx0) v00 = *reinterpret_cast<const float4*>(r0 + (size_t)x0 * DH);
        if (vy0 && vx1) v01 = *reinterpret_cast<const float4*>(r0 + (size_t)x1 * DH);
        if (vy1 && vx0) v10 = *reinterpret_cast<const float4*>(r1 + (size_t)x0 * DH);
        if (vy1 && vx1) v11 = *reinterpret_cast<const float4*>(r1 + (size_t)x1 * DH);

        acc.x += w00 * v00.x + w01 * v01.x + w10 * v10.x + w11 * v11.x;
        acc.y += w00 * v00.y + w01 * v01.y + w10 * v10.y + w11 * v11.y;
        acc.z += w00 * v00.z + w01 * v01.z + w10 * v10.z + w11 * v11.z;
        acc.w += w00 * v00.w + w01 * v01.w + w10 * v10.w + w11 * v11.w;
    }

    // reduce across the 4 point-groups (lanes xor 8, 16)
    #pragma unroll
    for (int off = 8; off <= 16; off <<= 1) {
        acc.x += __shfl_xor_sync(0xffffffffu, acc.x, off);
        acc.y += __shfl_xor_sync(0xffffffffu, acc.y, off);
        acc.z += __shfl_xor_sync(0xffffffffu, acc.z, off);
        acc.w += __shfl_xor_sync(0xffffffffu, acc.w, off);
    }
    if (lane < 8)
        *reinterpret_cast<float4*>(g_tmp + (size_t)bq * D + h * DH + cq) = acc;
}

// ---------------- launch ----------------
extern "C" void kernel_launch(void* const* d_in, const int* in_sizes, int n_in,
                              void* d_out, int out_size) {
    const float* query = (const float*)d_in[0];
    const float* value = (const float*)d_in[1];
    const float* refp  = (const float*)d_in[2];
    const float* Wv   = (const float*)d_in[5];
    const float* bv   = (const float*)d_in[6];
    const float* Wo   = (const float*)d_in[7];
    const float* bo   = (const float*)d_in[8];
    const float* Wa   = (const float*)d_in[9];
    const float* ba   = (const float*)d_in[10];
    const float* Wout = (const float*)d_in[11];
    const float* bout = (const float*)d_in[12];
    float* out = (float*)d_out;

    pack_w_kernel<<<(D * NFUSED + 255) / 256, 256>>>(Wo, bo, Wa, ba);

    gemm_tc<0><<<dim3(MR / 128, 256 / 64), 256>>>(value, Wv, bv, nullptr, nullptr, 256);
    gemm_tc<1><<<dim3(MR / 128, NFUSED / 64), 256>>>(query, nullptr, nullptr, nullptr, nullptr, NFUSED);

    sample_kernel<<<MR * NH / 8, 256>>>(refp);

    gemm_tc<2><<<dim3(MR / 128, 256 / 64), 256>>>(nullptr, Wout, bout, query, out, 256);
}

// round 12
// speedup vs baseline: 1.7941x; 1.1197x over previous
#include <cuda_runtime.h>
#include <cuda_fp16.h>
#include <cstdint>
#include <cstddef>

// ---------------- static problem shape ----------------
constexpr int BSZ = 2;
constexpr int NQ  = 21760;
constexpr int MR  = BSZ * NQ;      // 43520 rows
constexpr int D   = 256;
constexpr int NH  = 8;
constexpr int DH  = 32;
constexpr int NFUSED = 384;        // 256 offs + 128 attn logits

__device__ __constant__ int c_LW[4] = {128, 64, 32, 16};
__device__ __constant__ int c_LH[4] = {128, 64, 32, 16};
__device__ __constant__ int c_LS[4] = {0, 16384, 20480, 21504};

// ---------------- scratch ----------------
__device__ __half g_vth[(size_t)BSZ * NH * NQ * DH];    // v transposed: [b][h][pos][c] fp16
__device__ float  g_P [(size_t)MR * NFUSED];            // raw offs(256) + attn logits(128)
__device__ float  g_tmp[(size_t)MR * D];                // attention output before Wout
__device__ float  g_Wf[D * NFUSED];                     // fused [Wo | Wa]
__device__ float  g_bf[NFUSED];                         // fused [bo | ba]

// ---------------- helpers ----------------
__device__ __forceinline__ void mma_tf32(float& c0, float& c1, float& c2, float& c3,
                                         uint32_t a0, uint32_t a1, uint32_t a2, uint32_t a3,
                                         uint32_t b0, uint32_t b1) {
    asm volatile(
        "mma.sync.aligned.m16n8k8.row.col.f32.tf32.tf32.f32 "
        "{%0,%1,%2,%3}, {%4,%5,%6,%7}, {%8,%9}, {%0,%1,%2,%3};"
        : "+f"(c0), "+f"(c1), "+f"(c2), "+f"(c3)
        : "r"(a0), "r"(a1), "r"(a2), "r"(a3), "r"(b0), "r"(b1));
}

__device__ __forceinline__ void cp16(void* smem_dst, const void* gsrc) {
    unsigned d = (unsigned)__cvta_generic_to_shared(smem_dst);
    asm volatile("cp.async.cg.shared.global [%0], [%1], 16;" :: "r"(d), "l"(gsrc));
}

// ---------------- pack fused weight ----------------
__global__ void pack_w_kernel(const float* __restrict__ Wo, const float* __restrict__ bo,
                              const float* __restrict__ Wa, const float* __restrict__ ba) {
    int i = blockIdx.x * blockDim.x + threadIdx.x;
    if (i < D * NFUSED) {
        int k = i / NFUSED, n = i % NFUSED;
        g_Wf[i] = (n < 256) ? Wo[k * 256 + n] : Wa[k * 128 + (n - 256)];
    }
    if (i < NFUSED) g_bf[i] = (i < 256) ? bo[i] : ba[i - 256];
}

// ---------------- tf32 tensor-core GEMM, 3-stage cp.async pipeline ----------------
// Tile: BM=128, BN=64, BK=16.  8 warps as 4(M) x 2(N), warp tile 32x32.
// Both A and B fragments: raw fp32 bits (HW truncates to tf32) -- no cvt in loop.
// MODE 0: A=value, W=Wv   -> scatter into g_vth [b][h][pos][c] as fp16
// MODE 1: A=query, W=g_Wf -> g_P row-major
// MODE 2: A=g_tmp, W=Wout -> Cout = acc + bias + addin (residual)
template<int MODE>
__global__ __launch_bounds__(256)
void gemm_tc(const float* __restrict__ Ain, const float* __restrict__ Win,
             const float* __restrict__ biasin, const float* __restrict__ addin,
             float* __restrict__ Cout, int N)
{
    constexpr int K = D;
    const float* A    = (MODE == 2) ? g_tmp : Ain;
    const float* W    = (MODE == 1) ? g_Wf  : Win;
    const float* bias = (MODE == 1) ? g_bf  : biasin;

    __shared__ float As[3][128][20];   // [stage][m][k], stride 20 -> conflict-free
    __shared__ float Bs[3][16][72];    // [stage][k][n], stride 72 -> conflict-free

    const int tid  = threadIdx.x;
    const int warp = tid >> 5;
    const int lane = tid & 31;
    const int wm   = (warp & 3) * 32;
    const int wn   = (warp >> 2) * 32;
    const int m0   = blockIdx.x * 128;
    const int n0   = blockIdx.y * 64;

    const int ar = tid >> 2;   // 0..63 (and +64)
    const int aq = tid & 3;
    const int br = tid >> 4;   // 0..15
    const int bc = tid & 15;

    float c[2][4][4];
    #pragma unroll
    for (int mf = 0; mf < 2; ++mf)
        #pragma unroll
        for (int nf = 0; nf < 4; ++nf)
            #pragma unroll
            for (int i = 0; i < 4; ++i) c[mf][nf][i] = 0.f;

    auto load_stage = [&](int kt, int buf) {
        const int kk = kt * 16;
        cp16(&As[buf][ar][aq * 4],      A + (size_t)(m0 + ar) * K + kk + aq * 4);
        cp16(&As[buf][ar + 64][aq * 4], A + (size_t)(m0 + ar + 64) * K + kk + aq * 4);
        cp16(&Bs[buf][br][bc * 4],      W + (size_t)(kk + br) * N + n0 + bc * 4);
        asm volatile("cp.async.commit_group;" ::: "memory");
    };

    load_stage(0, 0);
    load_stage(1, 1);

    for (int kt = 0; kt < 16; ++kt) {
        const int buf = kt % 3;
        if (kt < 15) {
            asm volatile("cp.async.wait_group 1;" ::: "memory");
        } else {
            asm volatile("cp.async.wait_group 0;" ::: "memory");
        }
        __syncthreads();

        #pragma unroll
        for (int kc = 0; kc < 16; kc += 8) {
            uint32_t a[2][4], b[4][2];
            const int arow = wm + (lane >> 2);
            const int acol = kc + (lane & 3);
            #pragma unroll
            for (int mf = 0; mf < 2; ++mf) {
                const int r0 = arow + mf * 16;
                a[mf][0] = __float_as_uint(As[buf][r0    ][acol    ]);
                a[mf][1] = __float_as_uint(As[buf][r0 + 8][acol    ]);
                a[mf][2] = __float_as_uint(As[buf][r0    ][acol + 4]);
                a[mf][3] = __float_as_uint(As[buf][r0 + 8][acol + 4]);
            }
            #pragma unroll
            for (int nf = 0; nf < 4; ++nf) {
                const int nn = wn + nf * 8 + (lane >> 2);
                b[nf][0] = __float_as_uint(Bs[buf][acol    ][nn]);
                b[nf][1] = __float_as_uint(Bs[buf][acol + 4][nn]);
            }
            #pragma unroll
            for (int mf = 0; mf < 2; ++mf)
                #pragma unroll
                for (int nf = 0; nf < 4; ++nf)
                    mma_tf32(c[mf][nf][0], c[mf][nf][1], c[mf][nf][2], c[mf][nf][3],
                             a[mf][0], a[mf][1], a[mf][2], a[mf][3],
                             b[nf][0], b[nf][1]);
        }

        if (kt + 2 < 16) load_stage(kt + 2, (kt + 2) % 3);
    }

    // epilogue
    #pragma unroll
    for (int mf = 0; mf < 2; ++mf) {
        #pragma unroll
        for (int nf = 0; nf < 4; ++nf) {
            const int cb = n0 + wn + nf * 8 + 2 * (lane & 3);
            const float2 b2 = *reinterpret_cast<const float2*>(bias + cb);
            #pragma unroll
            for (int half_i = 0; half_i < 2; ++half_i) {
                const int row = m0 + wm + mf * 16 + (lane >> 2) + half_i * 8;
                const float v0 = c[mf][nf][half_i * 2 + 0] + b2.x;
                const float v1 = c[mf][nf][half_i * 2 + 1] + b2.y;
                if (MODE == 0) {
                    const int bb  = row / NQ;
                    const int pos = row - bb * NQ;
                    const __half2 hv = __floats2half2_rn(v0, v1);
                    *reinterpret_cast<__half2*>(
                        g_vth + ((size_t)(bb * NH + (cb >> 5)) * NQ + pos) * DH + (cb & 31)) = hv;
                } else if (MODE == 1) {
                    *reinterpret_cast<float2*>(g_P + (size_t)row * NFUSED + cb)
                        = make_float2(v0, v1);
                } else {
                    const float2 q2 = *reinterpret_cast<const float2*>(
                        addin + (size_t)row * D + cb);
                    *reinterpret_cast<float2*>(Cout + (size_t)row * D + cb)
                        = make_float2(v0 + q2.x, v1 + q2.y);
                }
            }
        }
    }
}

// ---------------- fused softmax + coords + bilinear gather ----------------
// R3/R7/R10 structure; v in fp16, weighted sum computed IN half2 (HFMA2):
// per corner 1 LDG.64 + 2 HFMA2 (was 1 LDG.128 + 4 FFMA) -- fewer instructions
// AND half the L1 bytes.  Reduction on 2 half2 regs (4 shuffles, was 8).
__global__ __launch_bounds__(256, 7)
void sample_kernel(const float* __restrict__ refp) {
    const int gwarp = blockIdx.x * 8 + (threadIdx.x >> 5);
    const int lane  = threadIdx.x & 31;
    if (gwarp >= MR * NH) return;
    const int h  = gwarp & 7;
    const int bq = gwarp >> 3;
    const int b  = (bq >= NQ);

    const float* Prow = g_P + (size_t)bq * NFUSED;
    const int i  = lane & 15;          // point index (lanes 16-31 mirror)
    const int il = i >> 2;

    // softmax over the 16 logits of this head
    float lg = Prow[256 + h * 16 + i];
    float mx = lg;
    #pragma unroll
    for (int off = 8; off; off >>= 1)
        mx = fmaxf(mx, __shfl_xor_sync(0xffffffffu, mx, off));
    float e = __expf(lg - mx);
    float ssum = e;
    #pragma unroll
    for (int off = 8; off; off >>= 1)
        ssum += __shfl_xor_sync(0xffffffffu, ssum, off);
    const float wgt = e / ssum;

    // pixel coords for this lane's point
    const float2 off2 = *reinterpret_cast<const float2*>(Prow + h * 32 + i * 2);
    const float2 ref2 = *reinterpret_cast<const float2*>(refp + (size_t)bq * 8 + il * 2);
    const float px = ref2.x * (float)c_LW[il] + off2.x - 0.5f;
    const float py = ref2.y * (float)c_LH[il] + off2.y - 0.5f;

    const int pgrp = lane >> 3;       // which point of the level this group does
    const int cq   = (lane & 7) * 4;  // channel quad
    const __half* vb = g_vth + ((size_t)(b * NH + h) * NQ) * DH + cq;

    __half2 acc01 = __float2half2_rn(0.f);
    __half2 acc23 = __float2half2_rn(0.f);
    #pragma unroll
    for (int j = 0; j < 4; ++j) {     // j = level
        const int Wl = c_LW[j], Hl = c_LH[j], st = c_LS[j];
        const int p  = j * 4 + pgrp;
        const float sx = __shfl_sync(0xffffffffu, px,  p);
        const float sy = __shfl_sync(0xffffffffu, py,  p);
        const float sw = __shfl_sync(0xffffffffu, wgt, p);

        const float xf = floorf(sx), yf = floorf(sy);
        const int   x0 = (int)xf,    y0 = (int)yf;
        const float wx1 = sx - xf,   wy1 = sy - yf;
        const float wx0 = 1.f - wx1, wy0 = 1.f - wy1;
        const int x1 = x0 + 1, y1 = y0 + 1;
        const bool vx0 = (unsigned)x0 < (unsigned)Wl;
        const bool vx1 = (unsigned)x1 < (unsigned)Wl;
        const bool vy0 = (unsigned)y0 < (unsigned)Hl;
        const bool vy1 = (unsigned)y1 < (unsigned)Hl;

        const float swy0 = sw * wy0;
        const float swy1 = sw * wy1;
        const __half2 w00h = __float2half2_rn(swy0 * wx0);
        const __half2 w01h = __float2half2_rn(swy0 * wx1);
        const __half2 w10h = __float2half2_rn(swy1 * wx0);
        const __half2 w11h = __float2half2_rn(swy1 * wx1);

        uint2 u00 = make_uint2(0u, 0u), u01 = u00, u10 = u00, u11 = u00;
        const __half* r0 = vb + (size_t)(st + y0 * Wl) * DH;
        const __half* r1 = vb + (size_t)(st + y1 * Wl) * DH;
        if (vy0 && vx0) u00 = *reinterpret_cast<const uint2*>(r0 + (size_t)x0 * DH);
        if (vy0 && vx1) u01 = *reinterpret_cast<const uint2*>(r0 + (size_t)x1 * DH);
        if (vy1 && vx0) u10 = *reinterpret_cast<const uint2*>(r1 + (size_t)x0 * DH);
        if (vy1 && vx1) u11 = *reinterpret_cast<const uint2*>(r1 + (size_t)x1 * DH);

        acc01 = __hfma2(*reinterpret_cast<const __half2*>(&u00.x), w00h, acc01);
        acc23 = __hfma2(*reinterpret_cast<const __half2*>(&u00.y), w00h, acc23);
        acc01 = __hfma2(*reinterpret_cast<const __half2*>(&u01.x), w01h, acc01);
        acc23 = __hfma2(*reinterpret_cast<const __half2*>(&u01.y), w01h, acc23);
        acc01 = __hfma2(*reinterpret_cast<const __half2*>(&u10.x), w10h, acc01);
        acc23 = __hfma2(*reinterpret_cast<const __half2*>(&u10.y), w10h, acc23);
        acc01 = __hfma2(*reinterpret_cast<const __half2*>(&u11.x), w11h, acc01);
        acc23 = __hfma2(*reinterpret_cast<const __half2*>(&u11.y), w11h, acc23);
    }

    // reduce across the 4 point-groups (lanes xor 8, 16)
    #pragma unroll
    for (int off = 8; off <= 16; off <<= 1) {
        uint32_t s01 = __shfl_xor_sync(0xffffffffu, *reinterpret_cast<uint32_t*>(&acc01), off);
        uint32_t s23 = __shfl_xor_sync(0xffffffffu, *reinterpret_cast<uint32_t*>(&acc23), off);
        acc01 = __hadd2(acc01, *reinterpret_cast<const __half2*>(&s01));
        acc23 = __hadd2(acc23, *reinterpret_cast<const __half2*>(&s23));
    }
    if (lane < 8) {
        const float2 f01 = __half22float2(acc01);
        const float2 f23 = __half22float2(acc23);
        *reinterpret_cast<float4*>(g_tmp + (size_t)bq * D + h * DH + cq)
            = make_float4(f01.x, f01.y, f23.x, f23.y);
    }
}

// ---------------- launch ----------------
extern "C" void kernel_launch(void* const* d_in, const int* in_sizes, int n_in,
                              void* d_out, int out_size) {
    const float* query = (const float*)d_in[0];
    const float* value = (const float*)d_in[1];
    const float* refp  = (const float*)d_in[2];
    const float* Wv   = (const float*)d_in[5];
    const float* bv   = (const float*)d_in[6];
    const float* Wo   = (const float*)d_in[7];
    const float* bo   = (const float*)d_in[8];
    const float* Wa   = (const float*)d_in[9];
    const float* ba   = (const float*)d_in[10];
    const float* Wout = (const float*)d_in[11];
    const float* bout = (const float*)d_in[12];
    float* out = (float*)d_out;

    pack_w_kernel<<<(D * NFUSED + 255) / 256, 256>>>(Wo, bo, Wa, ba);

    gemm_tc<0><<<dim3(MR / 128, 256 / 64), 256>>>(value, Wv, bv, nullptr, nullptr, 256);
    gemm_tc<1><<<dim3(MR / 128, NFUSED / 64), 256>>>(query, nullptr, nullptr, nullptr, nullptr, NFUSED);

    sample_kernel<<<MR * NH / 8, 256>>>(refp);

    gemm_tc<2><<<dim3(MR / 128, 256 / 64), 256>>>(nullptr, Wout, bout, query, out, 256);
}

// round 13
// speedup vs baseline: 1.8329x; 1.0216x over previous
#include <cuda_runtime.h>
#include <cuda_fp16.h>
#include <cstdint>
#include <cstddef>

// ---------------- static problem shape ----------------
constexpr int BSZ = 2;
constexpr int NQ  = 21760;
constexpr int MR  = BSZ * NQ;      // 43520 rows
constexpr int D   = 256;
constexpr int NH  = 8;
constexpr int DH  = 32;
constexpr int NFUSED = 384;        // 256 offs + 128 attn logits

__device__ __constant__ int c_LW[4] = {128, 64, 32, 16};
__device__ __constant__ int c_LH[4] = {128, 64, 32, 16};
__device__ __constant__ int c_LS[4] = {0, 16384, 20480, 21504};

// ---------------- scratch ----------------
__device__ __half g_vth[(size_t)BSZ * NH * NQ * DH];    // v transposed: [b][h][pos][c] fp16
__device__ float  g_P [(size_t)MR * NFUSED];            // raw offs(256) + attn logits(128)
__device__ float  g_tmp[(size_t)MR * D];                // attention output before Wout
__device__ float  g_Wf[D * NFUSED];                     // fused [Wo | Wa]
__device__ float  g_bf[NFUSED];                         // fused [bo | ba]

// ---------------- helpers ----------------
__device__ __forceinline__ void mma_tf32(float& c0, float& c1, float& c2, float& c3,
                                         uint32_t a0, uint32_t a1, uint32_t a2, uint32_t a3,
                                         uint32_t b0, uint32_t b1) {
    asm volatile(
        "mma.sync.aligned.m16n8k8.row.col.f32.tf32.tf32.f32 "
        "{%0,%1,%2,%3}, {%4,%5,%6,%7}, {%8,%9}, {%0,%1,%2,%3};"
        : "+f"(c0), "+f"(c1), "+f"(c2), "+f"(c3)
        : "r"(a0), "r"(a1), "r"(a2), "r"(a3), "r"(b0), "r"(b1));
}

__device__ __forceinline__ void cp16(void* smem_dst, const void* gsrc) {
    unsigned d = (unsigned)__cvta_generic_to_shared(smem_dst);
    asm volatile("cp.async.cg.shared.global [%0], [%1], 16;" :: "r"(d), "l"(gsrc));
}

// ---------------- pack fused weight ----------------
__global__ void pack_w_kernel(const float* __restrict__ Wo, const float* __restrict__ bo,
                              const float* __restrict__ Wa, const float* __restrict__ ba) {
    int i = blockIdx.x * blockDim.x + threadIdx.x;
    if (i < D * NFUSED) {
        int k = i / NFUSED, n = i % NFUSED;
        g_Wf[i] = (n < 256) ? Wo[k * 256 + n] : Wa[k * 128 + (n - 256)];
    }
    if (i < NFUSED) g_bf[i] = (i < 256) ? bo[i] : ba[i - 256];
}

// ---------------- merged mode0+mode1 tf32 GEMM (one launch, one tail) ----------------
// blockIdx.y < 4:  mode 0: A=value, W=Wv,   N=256    -> g_vth scatter (fp16)
// blockIdx.y >= 4: mode 1: A=query, W=g_Wf, N=NFUSED -> g_P row-major
// Inner loop identical to the validated 3-stage tf32 pipeline.
__global__ __launch_bounds__(256)
void gemm01_tc(const float* __restrict__ value, const float* __restrict__ query,
               const float* __restrict__ Wv, const float* __restrict__ bv)
{
    constexpr int K = D;
    const int mode = (blockIdx.y >= 4);
    const float* A    = mode ? query : value;
    const float* W    = mode ? g_Wf  : Wv;
    const float* bias = mode ? g_bf  : bv;
    const int N       = mode ? NFUSED : 256;
    const int n0      = (mode ? ((int)blockIdx.y - 4) : (int)blockIdx.y) * 64;

    __shared__ float As[3][128][20];   // [stage][m][k], stride 20 -> conflict-free
    __shared__ float Bs[3][16][72];    // [stage][k][n], stride 72 -> conflict-free

    const int tid  = threadIdx.x;
    const int warp = tid >> 5;
    const int lane = tid & 31;
    const int wm   = (warp & 3) * 32;
    const int wn   = (warp >> 2) * 32;
    const int m0   = blockIdx.x * 128;

    const int ar = tid >> 2;   // 0..63 (and +64)
    const int aq = tid & 3;
    const int br = tid >> 4;   // 0..15
    const int bc = tid & 15;

    float c[2][4][4];
    #pragma unroll
    for (int mf = 0; mf < 2; ++mf)
        #pragma unroll
        for (int nf = 0; nf < 4; ++nf)
            #pragma unroll
            for (int i = 0; i < 4; ++i) c[mf][nf][i] = 0.f;

    auto load_stage = [&](int kt, int buf) {
        const int kk = kt * 16;
        cp16(&As[buf][ar][aq * 4],      A + (size_t)(m0 + ar) * K + kk + aq * 4);
        cp16(&As[buf][ar + 64][aq * 4], A + (size_t)(m0 + ar + 64) * K + kk + aq * 4);
        cp16(&Bs[buf][br][bc * 4],      W + (size_t)(kk + br) * N + n0 + bc * 4);
        asm volatile("cp.async.commit_group;" ::: "memory");
    };

    load_stage(0, 0);
    load_stage(1, 1);

    for (int kt = 0; kt < 16; ++kt) {
        const int buf = kt % 3;
        if (kt < 15) {
            asm volatile("cp.async.wait_group 1;" ::: "memory");
        } else {
            asm volatile("cp.async.wait_group 0;" ::: "memory");
        }
        __syncthreads();

        #pragma unroll
        for (int kc = 0; kc < 16; kc += 8) {
            uint32_t a[2][4], b[4][2];
            const int arow = wm + (lane >> 2);
            const int acol = kc + (lane & 3);
            #pragma unroll
            for (int mf = 0; mf < 2; ++mf) {
                const int r0 = arow + mf * 16;
                a[mf][0] = __float_as_uint(As[buf][r0    ][acol    ]);
                a[mf][1] = __float_as_uint(As[buf][r0 + 8][acol    ]);
                a[mf][2] = __float_as_uint(As[buf][r0    ][acol + 4]);
                a[mf][3] = __float_as_uint(As[buf][r0 + 8][acol + 4]);
            }
            #pragma unroll
            for (int nf = 0; nf < 4; ++nf) {
                const int nn = wn + nf * 8 + (lane >> 2);
                b[nf][0] = __float_as_uint(Bs[buf][acol    ][nn]);
                b[nf][1] = __float_as_uint(Bs[buf][acol + 4][nn]);
            }
            #pragma unroll
            for (int mf = 0; mf < 2; ++mf)
                #pragma unroll
                for (int nf = 0; nf < 4; ++nf)
                    mma_tf32(c[mf][nf][0], c[mf][nf][1], c[mf][nf][2], c[mf][nf][3],
                             a[mf][0], a[mf][1], a[mf][2], a[mf][3],
                             b[nf][0], b[nf][1]);
        }

        if (kt + 2 < 16) load_stage(kt + 2, (kt + 2) % 3);
    }

    // epilogue
    #pragma unroll
    for (int mf = 0; mf < 2; ++mf) {
        #pragma unroll
        for (int nf = 0; nf < 4; ++nf) {
            const int cb = n0 + wn + nf * 8 + 2 * (lane & 3);
            const float2 b2 = *reinterpret_cast<const float2*>(bias + cb);
            #pragma unroll
            for (int half_i = 0; half_i < 2; ++half_i) {
                const int row = m0 + wm + mf * 16 + (lane >> 2) + half_i * 8;
                const float v0 = c[mf][nf][half_i * 2 + 0] + b2.x;
                const float v1 = c[mf][nf][half_i * 2 + 1] + b2.y;
                if (mode == 0) {
                    const int bb  = row / NQ;
                    const int pos = row - bb * NQ;
                    const __half2 hv = __floats2half2_rn(v0, v1);
                    *reinterpret_cast<__half2*>(
                        g_vth + ((size_t)(bb * NH + (cb >> 5)) * NQ + pos) * DH + (cb & 31)) = hv;
                } else {
                    *reinterpret_cast<float2*>(g_P + (size_t)row * NFUSED + cb)
                        = make_float2(v0, v1);
                }
            }
        }
    }
}

// ---------------- mode2 tf32 GEMM (unchanged from R11) ----------------
__global__ __launch_bounds__(256)
void gemm2_tc(const float* __restrict__ Win, const float* __restrict__ biasin,
              const float* __restrict__ addin, float* __restrict__ Cout)
{
    constexpr int K = D;
    constexpr int N = D;
    const float* A    = g_tmp;
    const float* W    = Win;
    const float* bias = biasin;

    __shared__ float As[3][128][20];
    __shared__ float Bs[3][16][72];

    const int tid  = threadIdx.x;
    const int warp = tid >> 5;
    const int lane = tid & 31;
    const int wm   = (warp & 3) * 32;
    const int wn   = (warp >> 2) * 32;
    const int m0   = blockIdx.x * 128;
    const int n0   = blockIdx.y * 64;

    const int ar = tid >> 2;
    const int aq = tid & 3;
    const int br = tid >> 4;
    const int bc = tid & 15;

    float c[2][4][4];
    #pragma unroll
    for (int mf = 0; mf < 2; ++mf)
        #pragma unroll
        for (int nf = 0; nf < 4; ++nf)
            #pragma unroll
            for (int i = 0; i < 4; ++i) c[mf][nf][i] = 0.f;

    auto load_stage = [&](int kt, int buf) {
        const int kk = kt * 16;
        cp16(&As[buf][ar][aq * 4],      A + (size_t)(m0 + ar) * K + kk + aq * 4);
        cp16(&As[buf][ar + 64][aq * 4], A + (size_t)(m0 + ar + 64) * K + kk + aq * 4);
        cp16(&Bs[buf][br][bc * 4],      W + (size_t)(kk + br) * N + n0 + bc * 4);
        asm volatile("cp.async.commit_group;" ::: "memory");
    };

    load_stage(0, 0);
    load_stage(1, 1);

    for (int kt = 0; kt < 16; ++kt) {
        const int buf = kt % 3;
        if (kt < 15) {
            asm volatile("cp.async.wait_group 1;" ::: "memory");
        } else {
            asm volatile("cp.async.wait_group 0;" ::: "memory");
        }
        __syncthreads();

        #pragma unroll
        for (int kc = 0; kc < 16; kc += 8) {
            uint32_t a[2][4], b[4][2];
            const int arow = wm + (lane >> 2);
            const int acol = kc + (lane & 3);
            #pragma unroll
            for (int mf = 0; mf < 2; ++mf) {
                const int r0 = arow + mf * 16;
                a[mf][0] = __float_as_uint(As[buf][r0    ][acol    ]);
                a[mf][1] = __float_as_uint(As[buf][r0 + 8][acol    ]);
                a[mf][2] = __float_as_uint(As[buf][r0    ][acol + 4]);
                a[mf][3] = __float_as_uint(As[buf][r0 + 8][acol + 4]);
            }
            #pragma unroll
            for (int nf = 0; nf < 4; ++nf) {
                const int nn = wn + nf * 8 + (lane >> 2);
                b[nf][0] = __float_as_uint(Bs[buf][acol    ][nn]);
                b[nf][1] = __float_as_uint(Bs[buf][acol + 4][nn]);
            }
            #pragma unroll
            for (int mf = 0; mf < 2; ++mf)
                #pragma unroll
                for (int nf = 0; nf < 4; ++nf)
                    mma_tf32(c[mf][nf][0], c[mf][nf][1], c[mf][nf][2], c[mf][nf][3],
                             a[mf][0], a[mf][1], a[mf][2], a[mf][3],
                             b[nf][0], b[nf][1]);
        }

        if (kt + 2 < 16) load_stage(kt + 2, (kt + 2) % 3);
    }

    #pragma unroll
    for (int mf = 0; mf < 2; ++mf) {
        #pragma unroll
        for (int nf = 0; nf < 4; ++nf) {
            const int cb = n0 + wn + nf * 8 + 2 * (lane & 3);
            const float2 b2 = *reinterpret_cast<const float2*>(bias + cb);
            #pragma unroll
            for (int half_i = 0; half_i < 2; ++half_i) {
                const int row = m0 + wm + mf * 16 + (lane >> 2) + half_i * 8;
                const float v0 = c[mf][nf][half_i * 2 + 0] + b2.x;
                const float v1 = c[mf][nf][half_i * 2 + 1] + b2.y;
                const float2 q2 = *reinterpret_cast<const float2*>(
                    addin + (size_t)row * D + cb);
                *reinterpret_cast<float2*>(Cout + (size_t)row * D + cb)
                    = make_float2(v0 + q2.x, v1 + q2.y);
            }
        }
    }
}

// ---------------- fused softmax + coords + bilinear gather (R11, unchanged) ----------------
__global__ __launch_bounds__(256, 7)
void sample_kernel(const float* __restrict__ refp) {
    const int gwarp = blockIdx.x * 8 + (threadIdx.x >> 5);
    const int lane  = threadIdx.x & 31;
    if (gwarp >= MR * NH) return;
    const int h  = gwarp & 7;
    const int bq = gwarp >> 3;
    const int b  = (bq >= NQ);

    const float* Prow = g_P + (size_t)bq * NFUSED;
    const int i  = lane & 15;          // point index (lanes 16-31 mirror)
    const int il = i >> 2;

    // softmax over the 16 logits of this head
    float lg = Prow[256 + h * 16 + i];
    float mx = lg;
    #pragma unroll
    for (int off = 8; off; off >>= 1)
        mx = fmaxf(mx, __shfl_xor_sync(0xffffffffu, mx, off));
    float e = __expf(lg - mx);
    float ssum = e;
    #pragma unroll
    for (int off = 8; off; off >>= 1)
        ssum += __shfl_xor_sync(0xffffffffu, ssum, off);
    const float wgt = e / ssum;

    // pixel coords for this lane's point
    const float2 off2 = *reinterpret_cast<const float2*>(Prow + h * 32 + i * 2);
    const float2 ref2 = *reinterpret_cast<const float2*>(refp + (size_t)bq * 8 + il * 2);
    const float px = ref2.x * (float)c_LW[il] + off2.x - 0.5f;
    const float py = ref2.y * (float)c_LH[il] + off2.y - 0.5f;

    const int pgrp = lane >> 3;       // which point of the level this group does
    const int cq   = (lane & 7) * 4;  // channel quad
    const __half* vb = g_vth + ((size_t)(b * NH + h) * NQ) * DH + cq;

    __half2 acc01 = __float2half2_rn(0.f);
    __half2 acc23 = __float2half2_rn(0.f);
    #pragma unroll
    for (int j = 0; j < 4; ++j) {     // j = level
        const int Wl = c_LW[j], Hl = c_LH[j], st = c_LS[j];
        const int p  = j * 4 + pgrp;
        const float sx = __shfl_sync(0xffffffffu, px,  p);
        const float sy = __shfl_sync(0xffffffffu, py,  p);
        const float sw = __shfl_sync(0xffffffffu, wgt, p);

        const float xf = floorf(sx), yf = floorf(sy);
        const int   x0 = (int)xf,    y0 = (int)yf;
        const float wx1 = sx - xf,   wy1 = sy - yf;
        const float wx0 = 1.f - wx1, wy0 = 1.f - wy1;
        const int x1 = x0 + 1, y1 = y0 + 1;
        const bool vx0 = (unsigned)x0 < (unsigned)Wl;
        const bool vx1 = (unsigned)x1 < (unsigned)Wl;
        const bool vy0 = (unsigned)y0 < (unsigned)Hl;
        const bool vy1 = (unsigned)y1 < (unsigned)Hl;

        const float swy0 = sw * wy0;
        const float swy1 = sw * wy1;
        const __half2 w00h = __float2half2_rn(swy0 * wx0);
        const __half2 w01h = __float2half2_rn(swy0 * wx1);
        const __half2 w10h = __float2half2_rn(swy1 * wx0);
        const __half2 w11h = __float2half2_rn(swy1 * wx1);

        uint2 u00 = make_uint2(0u, 0u), u01 = u00, u10 = u00, u11 = u00;
        const __half* r0 = vb + (size_t)(st + y0 * Wl) * DH;
        const __half* r1 = vb + (size_t)(st + y1 * Wl) * DH;
        if (vy0 && vx0) u00 = *reinterpret_cast<const uint2*>(r0 + (size_t)x0 * DH);
        if (vy0 && vx1) u01 = *reinterpret_cast<const uint2*>(r0 + (size_t)x1 * DH);
        if (vy1 && vx0) u10 = *reinterpret_cast<const uint2*>(r1 + (size_t)x0 * DH);
        if (vy1 && vx1) u11 = *reinterpret_cast<const uint2*>(r1 + (size_t)x1 * DH);

        acc01 = __hfma2(*reinterpret_cast<const __half2*>(&u00.x), w00h, acc01);
        acc23 = __hfma2(*reinterpret_cast<const __half2*>(&u00.y), w00h, acc23);
        acc01 = __hfma2(*reinterpret_cast<const __half2*>(&u01.x), w01h, acc01);
        acc23 = __hfma2(*reinterpret_cast<const __half2*>(&u01.y), w01h, acc23);
        acc01 = __hfma2(*reinterpret_cast<const __half2*>(&u10.x), w10h, acc01);
        acc23 = __hfma2(*reinterpret_cast<const __half2*>(&u10.y), w10h, acc23);
        acc01 = __hfma2(*reinterpret_cast<const __half2*>(&u11.x), w11h, acc01);
        acc23 = __hfma2(*reinterpret_cast<const __half2*>(&u11.y), w11h, acc23);
    }

    // reduce across the 4 point-groups (lanes xor 8, 16)
    #pragma unroll
    for (int off = 8; off <= 16; off <<= 1) {
        uint32_t s01 = __shfl_xor_sync(0xffffffffu, *reinterpret_cast<uint32_t*>(&acc01), off);
        uint32_t s23 = __shfl_xor_sync(0xffffffffu, *reinterpret_cast<uint32_t*>(&acc23), off);
        acc01 = __hadd2(acc01, *reinterpret_cast<const __half2*>(&s01));
        acc23 = __hadd2(acc23, *reinterpret_cast<const __half2*>(&s23));
    }
    if (lane < 8) {
        const float2 f01 = __half22float2(acc01);
        const float2 f23 = __half22float2(acc23);
        *reinterpret_cast<float4*>(g_tmp + (size_t)bq * D + h * DH + cq)
            = make_float4(f01.x, f01.y, f23.x, f23.y);
    }
}

// ---------------- launch ----------------
extern "C" void kernel_launch(void* const* d_in, const int* in_sizes, int n_in,
                              void* d_out, int out_size) {
    const float* query = (const float*)d_in[0];
    const float* value = (const float*)d_in[1];
    const float* refp  = (const float*)d_in[2];
    const float* Wv   = (const float*)d_in[5];
    const float* bv   = (const float*)d_in[6];
    const float* Wo   = (const float*)d_in[7];
    const float* bo   = (const float*)d_in[8];
    const float* Wa   = (const float*)d_in[9];
    const float* ba   = (const float*)d_in[10];
    const float* Wout = (const float*)d_in[11];
    const float* bout = (const float*)d_in[12];
    float* out = (float*)d_out;

    pack_w_kernel<<<(D * NFUSED + 255) / 256, 256>>>(Wo, bo, Wa, ba);

    // merged value-GEMM (y<4) + query-GEMM (y>=4): one launch, one tail
    gemm01_tc<<<dim3(MR / 128, 4 + NFUSED / 64), 256>>>(value, query, Wv, bv);

    sample_kernel<<<MR * NH / 8, 256>>>(refp);

    gemm2_tc<<<dim3(MR / 128, 256 / 64), 256>>>(Wout, bout, query, out);
}

// round 15
// speedup vs baseline: 1.8990x; 1.0361x over previous
#include <cuda_runtime.h>
#include <cuda_fp16.h>
#include <cstdint>
#include <cstddef>

// ---------------- static problem shape ----------------
constexpr int BSZ = 2;
constexpr int NQ  = 21760;
constexpr int MR  = BSZ * NQ;      // 43520 rows
constexpr int D   = 256;
constexpr int NH  = 8;
constexpr int DH  = 32;
constexpr int NFUSED = 384;        // 256 offs + 128 attn logits

__device__ __constant__ int c_LW[4] = {128, 64, 32, 16};
__device__ __constant__ int c_LH[4] = {128, 64, 32, 16};
__device__ __constant__ int c_LS[4] = {0, 16384, 20480, 21504};

// ---------------- scratch (16B-aligned __half globals: cp.async-safe) ----------------
__device__ __align__(16) __half g_vth[(size_t)BSZ * NH * NQ * DH];  // v^T [b][h][pos][c] fp16
__device__ float  g_P [(size_t)MR * NFUSED];            // raw offs(256) + attn logits(128)
__device__ __align__(16) __half g_tmph[(size_t)MR * D]; // attention output fp16
__device__ float  g_Wf[D * NFUSED];                     // fused [Wo | Wa] fp32
__device__ __align__(16) __half g_WoutT[D * D];         // Wout^T [n][k] fp16
__device__ float  g_bf[NFUSED];                         // fused [bo | ba]

// ---------------- helpers ----------------
__device__ __forceinline__ void mma_tf32(float& c0, float& c1, float& c2, float& c3,
                                         uint32_t a0, uint32_t a1, uint32_t a2, uint32_t a3,
                                         uint32_t b0, uint32_t b1) {
    asm volatile(
        "mma.sync.aligned.m16n8k8.row.col.f32.tf32.tf32.f32 "
        "{%0,%1,%2,%3}, {%4,%5,%6,%7}, {%8,%9}, {%0,%1,%2,%3};"
        : "+f"(c0), "+f"(c1), "+f"(c2), "+f"(c3)
        : "r"(a0), "r"(a1), "r"(a2), "r"(a3), "r"(b0), "r"(b1));
}

__device__ __forceinline__ void mma_f16_k8(float& c0, float& c1, float& c2, float& c3,
                                           uint32_t a0, uint32_t a1, uint32_t b0) {
    asm volatile(
        "mma.sync.aligned.m16n8k8.row.col.f32.f16.f16.f32 "
        "{%0,%1,%2,%3}, {%4,%5}, {%6}, {%0,%1,%2,%3};"
        : "+f"(c0), "+f"(c1), "+f"(c2), "+f"(c3)
        : "r"(a0), "r"(a1), "r"(b0));
}

__device__ __forceinline__ void cp16(void* smem_dst, const void* gsrc) {
    unsigned d = (unsigned)__cvta_generic_to_shared(smem_dst);
    asm volatile("cp.async.cg.shared.global [%0], [%1], 16;" :: "r"(d), "l"(gsrc));
}

// ---------------- pack: fused fp32 [Wo|Wa] + biases + fp16 Wout^T ----------------
__global__ void pack_w_kernel(const float* __restrict__ Wo, const float* __restrict__ bo,
                              const float* __restrict__ Wa, const float* __restrict__ ba,
                              const float* __restrict__ Wout) {
    int i = blockIdx.x * blockDim.x + threadIdx.x;
    if (i < NFUSED) g_bf[i] = (i < 256) ? bo[i] : ba[i - 256];
    if (i < D * NFUSED) {
        int k = i / NFUSED, n = i % NFUSED;
        g_Wf[i] = (n < 256) ? Wo[k * 256 + n] : Wa[k * 128 + (n - 256)];
    }
    int j = i - D * NFUSED;
    if (j >= 0 && j < 65536) {           // WoutT[n][k] = Wout[k][n]
        int n = j >> 8, k = j & 255;
        g_WoutT[j] = __float2half(Wout[k * 256 + n]);
    }
}

// ---------------- merged mode0+mode1 tf32 GEMM (R12, validated) ----------------
// blockIdx.y < 4:  mode 0: A=value, W=Wv,   N=256    -> g_vth scatter (fp16)
// blockIdx.y >= 4: mode 1: A=query, W=g_Wf, N=NFUSED -> g_P row-major
__global__ __launch_bounds__(256)
void gemm01_tc(const float* __restrict__ value, const float* __restrict__ query,
               const float* __restrict__ Wv, const float* __restrict__ bv)
{
    constexpr int K = D;
    const int mode = (blockIdx.y >= 4);
    const float* A    = mode ? query : value;
    const float* W    = mode ? g_Wf  : Wv;
    const float* bias = mode ? g_bf  : bv;
    const int N       = mode ? NFUSED : 256;
    const int n0      = (mode ? ((int)blockIdx.y - 4) : (int)blockIdx.y) * 64;

    __shared__ float As[3][128][20];   // [stage][m][k], stride 20 -> conflict-free
    __shared__ float Bs[3][16][72];    // [stage][k][n], stride 72 -> conflict-free

    const int tid  = threadIdx.x;
    const int warp = tid >> 5;
    const int lane = tid & 31;
    const int wm   = (warp & 3) * 32;
    const int wn   = (warp >> 2) * 32;
    const int m0   = blockIdx.x * 128;

    const int ar = tid >> 2;   // 0..63 (and +64)
    const int aq = tid & 3;
    const int br = tid >> 4;   // 0..15
    const int bc = tid & 15;

    float c[2][4][4];
    #pragma unroll
    for (int mf = 0; mf < 2; ++mf)
        #pragma unroll
        for (int nf = 0; nf < 4; ++nf)
            #pragma unroll
            for (int i = 0; i < 4; ++i) c[mf][nf][i] = 0.f;

    auto load_stage = [&](int kt, int buf) {
        const int kk = kt * 16;
        cp16(&As[buf][ar][aq * 4],      A + (size_t)(m0 + ar) * K + kk + aq * 4);
        cp16(&As[buf][ar + 64][aq * 4], A + (size_t)(m0 + ar + 64) * K + kk + aq * 4);
        cp16(&Bs[buf][br][bc * 4],      W + (size_t)(kk + br) * N + n0 + bc * 4);
        asm volatile("cp.async.commit_group;" ::: "memory");
    };

    load_stage(0, 0);
    load_stage(1, 1);

    for (int kt = 0; kt < 16; ++kt) {
        const int buf = kt % 3;
        if (kt < 15) {
            asm volatile("cp.async.wait_group 1;" ::: "memory");
        } else {
            asm volatile("cp.async.wait_group 0;" ::: "memory");
        }
        __syncthreads();

        #pragma unroll
        for (int kc = 0; kc < 16; kc += 8) {
            uint32_t a[2][4], b[4][2];
            const int arow = wm + (lane >> 2);
            const int acol = kc + (lane & 3);
            #pragma unroll
            for (int mf = 0; mf < 2; ++mf) {
                const int r0 = arow + mf * 16;
                a[mf][0] = __float_as_uint(As[buf][r0    ][acol    ]);
                a[mf][1] = __float_as_uint(As[buf][r0 + 8][acol    ]);
                a[mf][2] = __float_as_uint(As[buf][r0    ][acol + 4]);
                a[mf][3] = __float_as_uint(As[buf][r0 + 8][acol + 4]);
            }
            #pragma unroll
            for (int nf = 0; nf < 4; ++nf) {
                const int nn = wn + nf * 8 + (lane >> 2);
                b[nf][0] = __float_as_uint(Bs[buf][acol    ][nn]);
                b[nf][1] = __float_as_uint(Bs[buf][acol + 4][nn]);
            }
            #pragma unroll
            for (int mf = 0; mf < 2; ++mf)
                #pragma unroll
                for (int nf = 0; nf < 4; ++nf)
                    mma_tf32(c[mf][nf][0], c[mf][nf][1], c[mf][nf][2], c[mf][nf][3],
                             a[mf][0], a[mf][1], a[mf][2], a[mf][3],
                             b[nf][0], b[nf][1]);
        }

        if (kt + 2 < 16) load_stage(kt + 2, (kt + 2) % 3);
    }

    // epilogue
    #pragma unroll
    for (int mf = 0; mf < 2; ++mf) {
        #pragma unroll
        for (int nf = 0; nf < 4; ++nf) {
            const int cb = n0 + wn + nf * 8 + 2 * (lane & 3);
            const float2 b2 = *reinterpret_cast<const float2*>(bias + cb);
            #pragma unroll
            for (int half_i = 0; half_i < 2; ++half_i) {
                const int row = m0 + wm + mf * 16 + (lane >> 2) + half_i * 8;
                const float v0 = c[mf][nf][half_i * 2 + 0] + b2.x;
                const float v1 = c[mf][nf][half_i * 2 + 1] + b2.y;
                if (mode == 0) {
                    const int bb  = row / NQ;
                    const int pos = row - bb * NQ;
                    const __half2 hv = __floats2half2_rn(v0, v1);
                    *reinterpret_cast<__half2*>(
                        g_vth + ((size_t)(bb * NH + (cb >> 5)) * NQ + pos) * DH + (cb & 31)) = hv;
                } else {
                    *reinterpret_cast<float2*>(g_P + (size_t)row * NFUSED + cb)
                        = make_float2(v0, v1);
                }
            }
        }
    }
}

// ---------------- mode2 fp16 GEMM: out = g_tmph @ Wout + bout + query ----------------
// A [m][k] fp16, W^T [n][k] fp16; mma m16n8k8 f16 (fp32 accum).
// Fragment maps: a0=(g, 2t..2t+1), a1=(g+8, ...); b0=(2t..2t+1, n); C as tf32 k8.
__global__ __launch_bounds__(256)
void gemm2_tc(const float* __restrict__ biasin, const float* __restrict__ addin,
              float* __restrict__ Cout)
{
    constexpr int K = D;
    const __half* A  = g_tmph;
    const __half* Wt = g_WoutT;

    __shared__ __align__(16) __half As[3][128][24];  // 16 data + 8 pad halfs
    __shared__ __align__(16) __half Bs[3][64][24];

    const int tid  = threadIdx.x;
    const int warp = tid >> 5;
    const int lane = tid & 31;
    const int wm   = (warp & 3) * 32;
    const int wn   = (warp >> 2) * 32;
    const int m0   = blockIdx.x * 128;
    const int n0   = blockIdx.y * 64;

    const int lrow = tid >> 1;          // 0..127
    const int lseg = tid & 1;           // 8-half chunk

    float c[2][4][4];
    #pragma unroll
    for (int mf = 0; mf < 2; ++mf)
        #pragma unroll
        for (int nf = 0; nf < 4; ++nf)
            #pragma unroll
            for (int i = 0; i < 4; ++i) c[mf][nf][i] = 0.f;

    auto load_stage = [&](int kt, int buf) {
        const int kk = kt * 16;
        cp16(&As[buf][lrow][lseg * 8], A + (size_t)(m0 + lrow) * K + kk + lseg * 8);
        if (tid < 128)
            cp16(&Bs[buf][lrow][lseg * 8], Wt + (size_t)(n0 + lrow) * K + kk + lseg * 8);
        asm volatile("cp.async.commit_group;" ::: "memory");
    };

    load_stage(0, 0);
    load_stage(1, 1);

    const int qr = lane >> 2;
    const int t2 = (lane & 3) * 2;

    for (int kt = 0; kt < 16; ++kt) {
        const int buf = kt % 3;
        if (kt < 15) {
            asm volatile("cp.async.wait_group 1;" ::: "memory");
        } else {
            asm volatile("cp.async.wait_group 0;" ::: "memory");
        }
        __syncthreads();

        #pragma unroll
        for (int kc = 0; kc < 16; kc += 8) {
            uint32_t a[2][2], b[4];
            #pragma unroll
            for (int mf = 0; mf < 2; ++mf) {
                const int r0 = wm + qr + mf * 16;
                a[mf][0] = *reinterpret_cast<const uint32_t*>(&As[buf][r0    ][kc + t2]);
                a[mf][1] = *reinterpret_cast<const uint32_t*>(&As[buf][r0 + 8][kc + t2]);
            }
            #pragma unroll
            for (int nf = 0; nf < 4; ++nf) {
                const int nn = wn + nf * 8 + qr;
                b[nf] = *reinterpret_cast<const uint32_t*>(&Bs[buf][nn][kc + t2]);
            }
            #pragma unroll
            for (int mf = 0; mf < 2; ++mf)
                #pragma unroll
                for (int nf = 0; nf < 4; ++nf)
                    mma_f16_k8(c[mf][nf][0], c[mf][nf][1], c[mf][nf][2], c[mf][nf][3],
                               a[mf][0], a[mf][1], b[nf]);
        }

        if (kt + 2 < 16) load_stage(kt + 2, (kt + 2) % 3);
    }

    #pragma unroll
    for (int mf = 0; mf < 2; ++mf) {
        #pragma unroll
        for (int nf = 0; nf < 4; ++nf) {
            const int cb = n0 + wn + nf * 8 + 2 * (lane & 3);
            const float2 b2 = *reinterpret_cast<const float2*>(biasin + cb);
            #pragma unroll
            for (int half_i = 0; half_i < 2; ++half_i) {
                const int row = m0 + wm + mf * 16 + (lane >> 2) + half_i * 8;
                const float v0 = c[mf][nf][half_i * 2 + 0] + b2.x;
                const float v1 = c[mf][nf][half_i * 2 + 1] + b2.y;
                const float2 q2 = *reinterpret_cast<const float2*>(
                    addin + (size_t)row * D + cb);
                *reinterpret_cast<float2*>(Cout + (size_t)row * D + cb)
                    = make_float2(v0 + q2.x, v1 + q2.y);
            }
        }
    }
}

// ---------------- fused softmax + coords + bilinear gather (R12 compute; fp16 out) ----------------
__global__ __launch_bounds__(256, 8)
void sample_kernel(const float* __restrict__ refp) {
    const int gwarp = blockIdx.x * 8 + (threadIdx.x >> 5);
    const int lane  = threadIdx.x & 31;
    if (gwarp >= MR * NH) return;
    const int h  = gwarp & 7;
    const int bq = gwarp >> 3;
    const int b  = (bq >= NQ);

    const float* Prow = g_P + (size_t)bq * NFUSED;
    const int i  = lane & 15;          // point index (lanes 16-31 mirror)
    const int il = i >> 2;

    // softmax over the 16 logits of this head
    float lg = Prow[256 + h * 16 + i];
    float mx = lg;
    #pragma unroll
    for (int off = 8; off; off >>= 1)
        mx = fmaxf(mx, __shfl_xor_sync(0xffffffffu, mx, off));
    float e = __expf(lg - mx);
    float ssum = e;
    #pragma unroll
    for (int off = 8; off; off >>= 1)
        ssum += __shfl_xor_sync(0xffffffffu, ssum, off);
    const float wgt = e / ssum;

    // pixel coords for this lane's point
    const float2 off2 = *reinterpret_cast<const float2*>(Prow + h * 32 + i * 2);
    const float2 ref2 = *reinterpret_cast<const float2*>(refp + (size_t)bq * 8 + il * 2);
    const float px = ref2.x * (float)c_LW[il] + off2.x - 0.5f;
    const float py = ref2.y * (float)c_LH[il] + off2.y - 0.5f;

    const int pgrp = lane >> 3;       // which point of the level this group does
    const int cq   = (lane & 7) * 4;  // channel quad
    const __half* vb = g_vth + ((size_t)(b * NH + h) * NQ) * DH + cq;

    __half2 acc01 = __float2half2_rn(0.f);
    __half2 acc23 = __float2half2_rn(0.f);
    #pragma unroll
    for (int j = 0; j < 4; ++j) {     // j = level
        const int Wl = c_LW[j], Hl = c_LH[j], st = c_LS[j];
        const int p  = j * 4 + pgrp;
        const float sx = __shfl_sync(0xffffffffu, px,  p);
        const float sy = __shfl_sync(0xffffffffu, py,  p);
        const float sw = __shfl_sync(0xffffffffu, wgt, p);

        const float xf = floorf(sx), yf = floorf(sy);
        const int   x0 = (int)xf,    y0 = (int)yf;
        const float wx1 = sx - xf,   wy1 = sy - yf;
        const float wx0 = 1.f - wx1, wy0 = 1.f - wy1;
        const int x1 = x0 + 1, y1 = y0 + 1;
        const bool vx0 = (unsigned)x0 < (unsigned)Wl;
        const bool vx1 = (unsigned)x1 < (unsigned)Wl;
        const bool vy0 = (unsigned)y0 < (unsigned)Hl;
        const bool vy1 = (unsigned)y1 < (unsigned)Hl;

        const float swy0 = sw * wy0;
        const float swy1 = sw * wy1;
        const __half2 w00h = __float2half2_rn(swy0 * wx0);
        const __half2 w01h = __float2half2_rn(swy0 * wx1);
        const __half2 w10h = __float2half2_rn(swy1 * wx0);
        const __half2 w11h = __float2half2_rn(swy1 * wx1);

        uint2 u00 = make_uint2(0u, 0u), u01 = u00, u10 = u00, u11 = u00;
        const __half* r0 = vb + (size_t)(st + y0 * Wl) * DH;
        const __half* r1 = vb + (size_t)(st + y1 * Wl) * DH;
        if (vy0 && vx0) u00 = *reinterpret_cast<const uint2*>(r0 + (size_t)x0 * DH);
        if (vy0 && vx1) u01 = *reinterpret_cast<const uint2*>(r0 + (size_t)x1 * DH);
        if (vy1 && vx0) u10 = *reinterpret_cast<const uint2*>(r1 + (size_t)x0 * DH);
        if (vy1 && vx1) u11 = *reinterpret_cast<const uint2*>(r1 + (size_t)x1 * DH);

        acc01 = __hfma2(*reinterpret_cast<const __half2*>(&u00.x), w00h, acc01);
        acc23 = __hfma2(*reinterpret_cast<const __half2*>(&u00.y), w00h, acc23);
        acc01 = __hfma2(*reinterpret_cast<const __half2*>(&u01.x), w01h, acc01);
        acc23 = __hfma2(*reinterpret_cast<const __half2*>(&u01.y), w01h, acc23);
        acc01 = __hfma2(*reinterpret_cast<const __half2*>(&u10.x), w10h, acc01);
        acc23 = __hfma2(*reinterpret_cast<const __half2*>(&u10.y), w10h, acc23);
        acc01 = __hfma2(*reinterpret_cast<const __half2*>(&u11.x), w11h, acc01);
        acc23 = __hfma2(*reinterpret_cast<const __half2*>(&u11.y), w11h, acc23);
    }

    // reduce across the 4 point-groups (lanes xor 8, 16)
    #pragma unroll
    for (int off = 8; off <= 16; off <<= 1) {
        uint32_t s01 = __shfl_xor_sync(0xffffffffu, *reinterpret_cast<uint32_t*>(&acc01), off);
        uint32_t s23 = __shfl_xor_sync(0xffffffffu, *reinterpret_cast<uint32_t*>(&acc23), off);
        acc01 = __hadd2(acc01, *reinterpret_cast<const __half2*>(&s01));
        acc23 = __hadd2(acc23, *reinterpret_cast<const __half2*>(&s23));
    }
    if (lane < 8) {
        uint2 o;
        o.x = *reinterpret_cast<uint32_t*>(&acc01);
        o.y = *reinterpret_cast<uint32_t*>(&acc23);
        *reinterpret_cast<uint2*>(g_tmph + (size_t)bq * D + h * DH + cq) = o;
    }
}

// ---------------- launch ----------------
extern "C" void kernel_launch(void* const* d_in, const int* in_sizes, int n_in,
                              void* d_out, int out_size) {
    const float* query = (const float*)d_in[0];
    const float* value = (const float*)d_in[1];
    const float* refp  = (const float*)d_in[2];
    const float* Wv   = (const float*)d_in[5];
    const float* bv   = (const float*)d_in[6];
    const float* Wo   = (const float*)d_in[7];
    const float* bo   = (const float*)d_in[8];
    const float* Wa   = (const float*)d_in[9];
    const float* ba   = (const float*)d_in[10];
    const float* Wout = (const float*)d_in[11];
    const float* bout = (const float*)d_in[12];
    float* out = (float*)d_out;

    pack_w_kernel<<<(D * NFUSED + 65536 + 255) / 256, 256>>>(Wo, bo, Wa, ba, Wout);

    // merged value-GEMM (y<4) + query-GEMM (y>=4), tf32 (validated)
    gemm01_tc<<<dim3(MR / 128, 4 + NFUSED / 64), 256>>>(value, query, Wv, bv);

    sample_kernel<<<MR * NH / 8, 256>>>(refp);

    // fp16 bisection target: out = g_tmph @ Wout + bout + query
    gemm2_tc<<<dim3(MR / 128, 256 / 64), 256>>>(bout, query, out);
}